// round 9
// baseline (speedup 1.0000x reference)
#include <cuda_runtime.h>
#include <cuda_pipeline.h>
#include <math.h>

#define Bc 64
#define Sc 2048
#define Hc 512
#define Kc 1024
#define SCC 16
#define SCHUNK (Sc/SCC)   // 128
#define QB 16             // query rows per qproj CTA

// Scratch (no allocations allowed in kernel_launch)
__device__ float g_q[Bc*Hc];            // 128 KB
__device__ float g_scores[Bc*Sc];       // 512 KB
__device__ float g_part[SCC*Bc*Kc];     // 4 MB

// tanh(x) = 1 - 2/(exp(2x)+1); __expf ~2ulp -> overall ~1e-6 error.
__device__ __forceinline__ float fast_tanhf(float x) {
    float e = __expf(2.0f * x);
    return 1.0f - __fdividef(2.0f, e + 1.0f);
}

#if defined(__CUDA_ARCH__) && (__CUDA_ARCH__ >= 900)
#define GRID_DEP_SYNC() cudaGridDependencySynchronize()
#define PDL_TRIGGER()   cudaTriggerProgrammaticLaunchCompletion()
#else
#define GRID_DEP_SYNC()
#define PDL_TRIGGER()
#endif

// ---------------------------------------------------------------------------
// K1: q[b,h] = sum_e query[b,e] * W_q[h,e]
// grid (Hc/8, Bc/QB) = (64, 4), block 256. Triggers PDL at START so score's
// CTAs co-schedule and stage pk via cp.async while qproj computes.
// ---------------------------------------------------------------------------
__global__ void qproj_kernel(const float* __restrict__ query,
                             const float* __restrict__ Wq) {
    __shared__ float sq[QB][Hc];            // 32 KB
    const int t = threadIdx.x;
    if (t == 0) PDL_TRIGGER();              // successor may launch now
    const int warp = t >> 5, lane = t & 31;
    const int h  = blockIdx.x * 8 + warp;
    const int b0 = blockIdx.y * QB;

    const float4* wrow = (const float4*)(Wq + (size_t)h * Hc);
    float4 w0 = wrow[lane];
    float4 w1 = wrow[lane + 32];
    float4 w2 = wrow[lane + 64];
    float4 w3 = wrow[lane + 96];

    {
        const float4* qsrc = (const float4*)(query + (size_t)b0 * Hc);
        float4* qdst = (float4*)&sq[0][0];
#pragma unroll
        for (int j = 0; j < (QB*Hc/4)/256; j++)
            qdst[t + 256*j] = qsrc[t + 256*j];
    }
    __syncthreads();

#pragma unroll
    for (int bb = 0; bb < QB; bb++) {
        const float* qr = sq[bb];
        int e0 = lane*4, e1 = (lane+32)*4, e2 = (lane+64)*4, e3 = (lane+96)*4;
        float acc;
        acc = w0.x*qr[e0]   + w0.y*qr[e0+1] + w0.z*qr[e0+2] + w0.w*qr[e0+3];
        acc = fmaf(w1.x, qr[e1], acc); acc = fmaf(w1.y, qr[e1+1], acc);
        acc = fmaf(w1.z, qr[e1+2], acc); acc = fmaf(w1.w, qr[e1+3], acc);
        acc = fmaf(w2.x, qr[e2], acc); acc = fmaf(w2.y, qr[e2+1], acc);
        acc = fmaf(w2.z, qr[e2+2], acc); acc = fmaf(w2.w, qr[e2+3], acc);
        acc = fmaf(w3.x, qr[e3], acc); acc = fmaf(w3.y, qr[e3+1], acc);
        acc = fmaf(w3.z, qr[e3+2], acc); acc = fmaf(w3.w, qr[e3+3], acc);
#pragma unroll
        for (int o = 16; o; o >>= 1) acc += __shfl_xor_sync(0xffffffffu, acc, o);
        if (lane == 0) g_q[(b0 + bb)*Hc + h] = acc;
    }
}

// dot-accumulate two score rows (pointers may be smem or gmem)
__device__ __forceinline__ void score_rows(const float4* __restrict__ pA,
                                           const float4* __restrict__ pB,
                                           const float* __restrict__ sq,
                                           const float* __restrict__ sv,
                                           int lane, float& accA, float& accB) {
#pragma unroll
    for (int i = 0; i < 4; i++) {
        float4 a = pA[lane + 32*i];
        float4 c = pB[lane + 32*i];
        int e = (lane + 32*i) * 4;
        float q0 = sq[e], q1 = sq[e+1], q2 = sq[e+2], q3 = sq[e+3];
        float v0 = sv[e], v1 = sv[e+1], v2 = sv[e+2], v3 = sv[e+3];
        accA = fmaf(fast_tanhf(a.x + q0), v0, accA);
        accA = fmaf(fast_tanhf(a.y + q1), v1, accA);
        accA = fmaf(fast_tanhf(a.z + q2), v2, accA);
        accA = fmaf(fast_tanhf(a.w + q3), v3, accA);
        accB = fmaf(fast_tanhf(c.x + q0), v0, accB);
        accB = fmaf(fast_tanhf(c.y + q1), v1, accB);
        accB = fmaf(fast_tanhf(c.z + q2), v2, accB);
        accB = fmaf(fast_tanhf(c.w + q3), v3, accB);
    }
}

// ---------------------------------------------------------------------------
// K2: scores[b,s] = sum_h tanh(q[b,h] + pk[b,s,h]) * v[h]
// block 256 (8 warps), 16 rows/block. Rows 0-7 are cp.async-staged to smem
// BEFORE the grid-dep sync (fills qproj's window with pk's DRAM stream,
// no registers held). Warps 0-3 compute from smem, warps 4-7 from gmem.
// ---------------------------------------------------------------------------
__global__ void score_kernel(const float* __restrict__ pk,
                             const float* __restrict__ v) {
    __shared__ float4 st[8 * (Hc/4)];       // 16 KB: rows row0..row0+7
    __shared__ float sq[Hc];
    __shared__ float sv[Hc];
    const int t = threadIdx.x;
    const int row0 = blockIdx.x * 16;
    const int b = row0 >> 11;               // blocks don't straddle b

    // pre-sync: async-stage first 8 rows (contiguous 1024 float4)
    {
        const float4* src = (const float4*)(pk + (size_t)row0 * Hc);
#pragma unroll
        for (int j = 0; j < 4; j++)
            __pipeline_memcpy_async(&st[t + 256*j], src + t + 256*j, 16);
        __pipeline_commit();
    }
    sv[t]       = v[t];                     // input: no dependency
    sv[t + 256] = v[t + 256];

    GRID_DEP_SYNC();                        // wait for qproj's g_q
    sq[t]       = g_q[b*Hc + t];
    sq[t + 256] = g_q[b*Hc + t + 256];
    __pipeline_wait_prior(0);
    __syncthreads();

    const int warp = t >> 5, lane = t & 31;
    float accA = 0.0f, accB = 0.0f;
    int rowA, rowB;
    if (warp < 4) {                         // rows 0-7: from smem
        rowA = row0 + warp*2;
        rowB = rowA + 1;
        score_rows(st + (warp*2) * (Hc/4), st + (warp*2+1) * (Hc/4),
                   sq, sv, lane, accA, accB);
    } else {                                // rows 8-15: direct gmem
        rowA = row0 + 8 + (warp-4)*2;
        rowB = rowA + 1;
        score_rows((const float4*)(pk + (size_t)rowA * Hc),
                   (const float4*)(pk + (size_t)rowB * Hc),
                   sq, sv, lane, accA, accB);
    }
#pragma unroll
    for (int o = 16; o; o >>= 1) {
        accA += __shfl_xor_sync(0xffffffffu, accA, o);
        accB += __shfl_xor_sync(0xffffffffu, accB, o);
    }
    if (lane == 0) {
        g_scores[rowA] = accA;
        g_scores[rowB] = accB;
    }
}

// ---------------------------------------------------------------------------
// K3: masked softmax over s for each b. grid Bc, block 256, 8 values/thread.
// Triggers PDL at START so context CTAs co-schedule and stage eh.
// ---------------------------------------------------------------------------
__global__ void softmax_kernel(const int* __restrict__ mask,
                               float* __restrict__ alphas_out) {
    const int b = blockIdx.x, t = threadIdx.x;
    __shared__ float red[8];
    if (t == 0) PDL_TRIGGER();              // successor may launch now

    int m[8];
#pragma unroll
    for (int i = 0; i < 8; i++) m[i] = mask[b*Sc + t + 256*i];

    GRID_DEP_SYNC();                        // wait for g_scores

    float vals[8];
    float mx = -INFINITY;
#pragma unroll
    for (int i = 0; i < 8; i++) {
        float x = g_scores[b*Sc + t + 256*i];
        if (m[i] == 0) x = -INFINITY;
        vals[i] = x;
        mx = fmaxf(mx, x);
    }
#pragma unroll
    for (int o = 16; o; o >>= 1) mx = fmaxf(mx, __shfl_xor_sync(0xffffffffu, mx, o));
    if ((t & 31) == 0) red[t >> 5] = mx;
    __syncthreads();
    mx = red[0];
#pragma unroll
    for (int i = 1; i < 8; i++) mx = fmaxf(mx, red[i]);

    float sum = 0.0f;
#pragma unroll
    for (int i = 0; i < 8; i++) {
        float e = __expf(vals[i] - mx);
        vals[i] = e;
        sum += e;
    }
#pragma unroll
    for (int o = 16; o; o >>= 1) sum += __shfl_xor_sync(0xffffffffu, sum, o);
    __syncthreads();
    if ((t & 31) == 0) red[t >> 5] = sum;
    __syncthreads();
    float tot = red[0];
#pragma unroll
    for (int i = 1; i < 8; i++) tot += red[i];
    float inv = 1.0f / tot;
#pragma unroll
    for (int i = 0; i < 8; i++)
        alphas_out[b*Sc + t + 256*i] = vals[i] * inv;
}

// ---------------------------------------------------------------------------
// K4: partial context. grid (SCC, Bc) = (16, 64), block 256.
// First 4 eh rows cp.async-staged to smem BEFORE the grid-dep sync (fills
// softmax's window). Rows 4-127 identical to R4 hot loop.
// ---------------------------------------------------------------------------
__global__ void context_partial_kernel(const float* __restrict__ eh,
                                       const float* __restrict__ alphas) {
    __shared__ float4 est[4 * (Kc/4)];      // 16 KB: rows 0-3 of this chunk
    __shared__ float sa[SCHUNK];
    const int c = blockIdx.x;
    const int b = blockIdx.y;
    const int t = threadIdx.x;

    const float4* base = (const float4*)(eh + ((size_t)(b*Sc + c*SCHUNK)) * Kc);

    // pre-sync: async-stage first 4 rows (contiguous 1024 float4)
#pragma unroll
    for (int j = 0; j < 4; j++)
        __pipeline_memcpy_async(&est[t + 256*j], base + t + 256*j, 16);
    __pipeline_commit();

    GRID_DEP_SYNC();                        // wait for alphas (softmax output)
    if (t < SCHUNK) sa[t] = alphas[b*Sc + c*SCHUNK + t];
    __pipeline_wait_prior(0);
    __syncthreads();

    float4 acc;
    {
        float4 r0 = est[0*(Kc/4) + t];
        float4 r1 = est[1*(Kc/4) + t];
        float4 r2 = est[2*(Kc/4) + t];
        float4 r3 = est[3*(Kc/4) + t];
        acc.x = sa[0]*r0.x; acc.y = sa[0]*r0.y;
        acc.z = sa[0]*r0.z; acc.w = sa[0]*r0.w;
        acc.x = fmaf(sa[1], r1.x, acc.x); acc.y = fmaf(sa[1], r1.y, acc.y);
        acc.z = fmaf(sa[1], r1.z, acc.z); acc.w = fmaf(sa[1], r1.w, acc.w);
        acc.x = fmaf(sa[2], r2.x, acc.x); acc.y = fmaf(sa[2], r2.y, acc.y);
        acc.z = fmaf(sa[2], r2.z, acc.z); acc.w = fmaf(sa[2], r2.w, acc.w);
        acc.x = fmaf(sa[3], r3.x, acc.x); acc.y = fmaf(sa[3], r3.y, acc.y);
        acc.z = fmaf(sa[3], r3.z, acc.z); acc.w = fmaf(sa[3], r3.w, acc.w);
    }

    const float4* p = base + t;
#pragma unroll 8
    for (int s = 4; s < SCHUNK; s++) {
        float a = sa[s];
        float4 vv = p[(size_t)s * (Kc/4)];
        acc.x = fmaf(a, vv.x, acc.x);
        acc.y = fmaf(a, vv.y, acc.y);
        acc.z = fmaf(a, vv.z, acc.z);
        acc.w = fmaf(a, vv.w, acc.w);
    }
    ((float4*)g_part)[((size_t)c*Bc + b) * (Kc/4) + t] = acc;
}

// ---------------------------------------------------------------------------
// K5: reduce 16 partials -> context. grid Bc, block 256 (float4 per thread).
// ---------------------------------------------------------------------------
__global__ void context_reduce_kernel(float* __restrict__ ctx_out) {
    const int b = blockIdx.x, t = threadIdx.x;
    GRID_DEP_SYNC();                        // wait for g_part
    float4 acc = make_float4(0.f, 0.f, 0.f, 0.f);
#pragma unroll
    for (int c = 0; c < SCC; c++) {
        float4 v = ((const float4*)g_part)[((size_t)c*Bc + b) * (Kc/4) + t];
        acc.x += v.x; acc.y += v.y; acc.z += v.z; acc.w += v.w;
    }
    ((float4*)ctx_out)[(size_t)b * (Kc/4) + t] = acc;
}

// ---------------------------------------------------------------------------
template <typename K, typename... Args>
static inline void launch_pdl(K kernel, dim3 grid, dim3 block, Args... args) {
    cudaLaunchAttribute attr[1];
    attr[0].id = cudaLaunchAttributeProgrammaticStreamSerialization;
    attr[0].val.programmaticStreamSerializationAllowed = 1;
    cudaLaunchConfig_t cfg;
    cfg.gridDim = grid;
    cfg.blockDim = block;
    cfg.dynamicSmemBytes = 0;
    cfg.stream = 0;
    cfg.attrs = attr;
    cfg.numAttrs = 1;
    cudaLaunchKernelEx(&cfg, kernel, args...);
}

extern "C" void kernel_launch(void* const* d_in, const int* in_sizes, int n_in,
                              void* d_out, int out_size) {
    const float* query    = (const float*)d_in[0]; // (B,1,H)
    const float* proj_key = (const float*)d_in[1]; // (B,S,H)
    const float* enc      = (const float*)d_in[2]; // (B,S,K)
    const int*   mask     = (const int*)  d_in[3]; // (B,1,S)
    const float* Wq       = (const float*)d_in[4]; // (H,H)
    const float* v        = (const float*)d_in[5]; // (H,)

    float* ctx    = (float*)d_out;              // (B,1,K)
    float* alphas = (float*)d_out + Bc*Kc;      // (B,1,S)

    qproj_kernel<<<dim3(Hc/8, Bc/QB), 256>>>(query, Wq);
    launch_pdl(score_kernel,           dim3((Bc*Sc)/16), dim3(256), proj_key, v);
    launch_pdl(softmax_kernel,         dim3(Bc),         dim3(256), mask, alphas);
    launch_pdl(context_partial_kernel, dim3(SCC, Bc),    dim3(256), enc, (const float*)alphas);
    launch_pdl(context_reduce_kernel,  dim3(Bc),         dim3(256), ctx);
}

// round 10
// speedup vs baseline: 1.0641x; 1.0641x over previous
#include <cuda_runtime.h>
#include <math.h>

#define Bc 64
#define Sc 2048
#define Hc 512
#define Kc 1024
#define SCC 16
#define SCHUNK (Sc/SCC)   // 128
#define QB 16             // query rows per qproj CTA

// Scratch (no allocations allowed in kernel_launch)
__device__ float g_q[Bc*Hc];            // 128 KB
__device__ float g_scores[Bc*Sc];       // 512 KB
__device__ float g_part[SCC*Bc*Kc];     // 4 MB

// tanh(x) = 1 - 2/(exp(2x)+1); __expf ~2ulp -> overall ~1e-6 error.
__device__ __forceinline__ float fast_tanhf(float x) {
    float e = __expf(2.0f * x);
    return 1.0f - __fdividef(2.0f, e + 1.0f);
}

#if defined(__CUDA_ARCH__) && (__CUDA_ARCH__ >= 900)
#define GRID_DEP_SYNC() cudaGridDependencySynchronize()
#else
#define GRID_DEP_SYNC()
#endif

// ---------------------------------------------------------------------------
// K1: q[b,h] = sum_e query[b,e] * W_q[h,e]
// grid (Hc/8, Bc/QB) = (64, 4), block 256 (8 warps).
// Warp keeps its W_q row in registers, dots against QB query rows in smem
// (W_q L2 traffic 4 MB instead of 64 MB).
// ---------------------------------------------------------------------------
__global__ void qproj_kernel(const float* __restrict__ query,
                             const float* __restrict__ Wq) {
    __shared__ float sq[QB][Hc];            // 32 KB
    const int t = threadIdx.x;
    const int warp = t >> 5, lane = t & 31;
    const int h  = blockIdx.x * 8 + warp;
    const int b0 = blockIdx.y * QB;

    const float4* wrow = (const float4*)(Wq + (size_t)h * Hc);
    float4 w0 = wrow[lane];
    float4 w1 = wrow[lane + 32];
    float4 w2 = wrow[lane + 64];
    float4 w3 = wrow[lane + 96];

    {
        const float4* qsrc = (const float4*)(query + (size_t)b0 * Hc);
        float4* qdst = (float4*)&sq[0][0];
#pragma unroll
        for (int j = 0; j < (QB*Hc/4)/256; j++)
            qdst[t + 256*j] = qsrc[t + 256*j];
    }
    __syncthreads();

#pragma unroll
    for (int bb = 0; bb < QB; bb++) {
        const float* qr = sq[bb];
        int e0 = lane*4, e1 = (lane+32)*4, e2 = (lane+64)*4, e3 = (lane+96)*4;
        float acc;
        acc = w0.x*qr[e0]   + w0.y*qr[e0+1] + w0.z*qr[e0+2] + w0.w*qr[e0+3];
        acc = fmaf(w1.x, qr[e1], acc); acc = fmaf(w1.y, qr[e1+1], acc);
        acc = fmaf(w1.z, qr[e1+2], acc); acc = fmaf(w1.w, qr[e1+3], acc);
        acc = fmaf(w2.x, qr[e2], acc); acc = fmaf(w2.y, qr[e2+1], acc);
        acc = fmaf(w2.z, qr[e2+2], acc); acc = fmaf(w2.w, qr[e2+3], acc);
        acc = fmaf(w3.x, qr[e3], acc); acc = fmaf(w3.y, qr[e3+1], acc);
        acc = fmaf(w3.z, qr[e3+2], acc); acc = fmaf(w3.w, qr[e3+3], acc);
#pragma unroll
        for (int o = 16; o; o >>= 1) acc += __shfl_xor_sync(0xffffffffu, acc, o);
        if (lane == 0) g_q[(b0 + bb)*Hc + h] = acc;
    }
}

// ---------------------------------------------------------------------------
// K2: scores[b,s] = sum_h tanh(q[b,h] + pk[b,s,h]) * v[h]
// block 256 (8 warps), warp handles 2 rows -> 16 rows/block, 8192 blocks.
// q[b,:] and v in smem; pk streamed once at ~6.7 TB/s.
// ---------------------------------------------------------------------------
__global__ void score_kernel(const float* __restrict__ pk,
                             const float* __restrict__ v) {
    __shared__ float sq[Hc];
    __shared__ float sv[Hc];
    const int t = threadIdx.x;
    const int row0 = blockIdx.x * 16;
    const int b = row0 >> 11;               // blocks don't straddle b
    sv[t]       = v[t];                     // input: no dependency
    sv[t + 256] = v[t + 256];
    GRID_DEP_SYNC();                        // wait for qproj's g_q
    sq[t]       = g_q[b*Hc + t];
    sq[t + 256] = g_q[b*Hc + t + 256];
    __syncthreads();

    const int warp = t >> 5, lane = t & 31;
    const int rowA = row0 + warp*2;
    const int rowB = rowA + 1;
    const float4* pA = (const float4*)(pk + (size_t)rowA * Hc);
    const float4* pB = (const float4*)(pk + (size_t)rowB * Hc);
    float accA = 0.0f, accB = 0.0f;
#pragma unroll
    for (int i = 0; i < 4; i++) {
        float4 a = pA[lane + 32*i];
        float4 c = pB[lane + 32*i];
        int e = (lane + 32*i) * 4;
        float q0 = sq[e], q1 = sq[e+1], q2 = sq[e+2], q3 = sq[e+3];
        float v0 = sv[e], v1 = sv[e+1], v2 = sv[e+2], v3 = sv[e+3];
        accA = fmaf(fast_tanhf(a.x + q0), v0, accA);
        accA = fmaf(fast_tanhf(a.y + q1), v1, accA);
        accA = fmaf(fast_tanhf(a.z + q2), v2, accA);
        accA = fmaf(fast_tanhf(a.w + q3), v3, accA);
        accB = fmaf(fast_tanhf(c.x + q0), v0, accB);
        accB = fmaf(fast_tanhf(c.y + q1), v1, accB);
        accB = fmaf(fast_tanhf(c.z + q2), v2, accB);
        accB = fmaf(fast_tanhf(c.w + q3), v3, accB);
    }
#pragma unroll
    for (int o = 16; o; o >>= 1) {
        accA += __shfl_xor_sync(0xffffffffu, accA, o);
        accB += __shfl_xor_sync(0xffffffffu, accB, o);
    }
    if (lane == 0) {
        g_scores[rowA] = accA;
        g_scores[rowB] = accB;
    }
}

// ---------------------------------------------------------------------------
// K3: masked softmax over s for each b. grid Bc, block 256, 8 values/thread.
// ---------------------------------------------------------------------------
__global__ void softmax_kernel(const int* __restrict__ mask,
                               float* __restrict__ alphas_out) {
    const int b = blockIdx.x, t = threadIdx.x;
    __shared__ float red[8];

    int m[8];
#pragma unroll
    for (int i = 0; i < 8; i++) m[i] = mask[b*Sc + t + 256*i];

    GRID_DEP_SYNC();                        // wait for g_scores

    float vals[8];
    float mx = -INFINITY;
#pragma unroll
    for (int i = 0; i < 8; i++) {
        float x = g_scores[b*Sc + t + 256*i];
        if (m[i] == 0) x = -INFINITY;
        vals[i] = x;
        mx = fmaxf(mx, x);
    }
#pragma unroll
    for (int o = 16; o; o >>= 1) mx = fmaxf(mx, __shfl_xor_sync(0xffffffffu, mx, o));
    if ((t & 31) == 0) red[t >> 5] = mx;
    __syncthreads();
    mx = red[0];
#pragma unroll
    for (int i = 1; i < 8; i++) mx = fmaxf(mx, red[i]);

    float sum = 0.0f;
#pragma unroll
    for (int i = 0; i < 8; i++) {
        float e = __expf(vals[i] - mx);
        vals[i] = e;
        sum += e;
    }
#pragma unroll
    for (int o = 16; o; o >>= 1) sum += __shfl_xor_sync(0xffffffffu, sum, o);
    __syncthreads();
    if ((t & 31) == 0) red[t >> 5] = sum;
    __syncthreads();
    float tot = red[0];
#pragma unroll
    for (int i = 1; i < 8; i++) tot += red[i];
    float inv = 1.0f / tot;
#pragma unroll
    for (int i = 0; i < 8; i++)
        alphas_out[b*Sc + t + 256*i] = vals[i] * inv;
}

// ---------------------------------------------------------------------------
// K4: partial context. grid (SCC, Bc) = (16, 64), block 256.
// Thread t owns float4 k-slot t (256 float4 = full K). Coalesced 4 KB rows,
// unroll 8 for MLP; 1024 CTAs keep occupancy >80%.
// ---------------------------------------------------------------------------
__global__ void context_partial_kernel(const float* __restrict__ eh,
                                       const float* __restrict__ alphas) {
    __shared__ float sa[SCHUNK];
    const int c = blockIdx.x;
    const int b = blockIdx.y;
    const int t = threadIdx.x;

    GRID_DEP_SYNC();                        // wait for alphas (softmax output)
    if (t < SCHUNK) sa[t] = alphas[b*Sc + c*SCHUNK + t];
    __syncthreads();

    const float4* base = (const float4*)(eh + ((size_t)(b*Sc + c*SCHUNK)) * Kc) + t;
    float4 acc = make_float4(0.f, 0.f, 0.f, 0.f);
#pragma unroll 8
    for (int s = 0; s < SCHUNK; s++) {
        float a = sa[s];
        float4 vv = base[(size_t)s * (Kc/4)];
        acc.x = fmaf(a, vv.x, acc.x);
        acc.y = fmaf(a, vv.y, acc.y);
        acc.z = fmaf(a, vv.z, acc.z);
        acc.w = fmaf(a, vv.w, acc.w);
    }
    ((float4*)g_part)[((size_t)c*Bc + b) * (Kc/4) + t] = acc;
}

// ---------------------------------------------------------------------------
// K5: reduce 16 partials -> context. grid Bc, block 256 (float4 per thread).
// ---------------------------------------------------------------------------
__global__ void context_reduce_kernel(float* __restrict__ ctx_out) {
    const int b = blockIdx.x, t = threadIdx.x;
    GRID_DEP_SYNC();                        // wait for g_part
    float4 acc = make_float4(0.f, 0.f, 0.f, 0.f);
#pragma unroll
    for (int c = 0; c < SCC; c++) {
        float4 v = ((const float4*)g_part)[((size_t)c*Bc + b) * (Kc/4) + t];
        acc.x += v.x; acc.y += v.y; acc.z += v.z; acc.w += v.w;
    }
    ((float4*)ctx_out)[(size_t)b * (Kc/4) + t] = acc;
}

// ---------------------------------------------------------------------------
template <typename K, typename... Args>
static inline void launch_pdl(K kernel, dim3 grid, dim3 block, Args... args) {
    cudaLaunchAttribute attr[1];
    attr[0].id = cudaLaunchAttributeProgrammaticStreamSerialization;
    attr[0].val.programmaticStreamSerializationAllowed = 1;
    cudaLaunchConfig_t cfg;
    cfg.gridDim = grid;
    cfg.blockDim = block;
    cfg.dynamicSmemBytes = 0;
    cfg.stream = 0;
    cfg.attrs = attr;
    cfg.numAttrs = 1;
    cudaLaunchKernelEx(&cfg, kernel, args...);
}

extern "C" void kernel_launch(void* const* d_in, const int* in_sizes, int n_in,
                              void* d_out, int out_size) {
    const float* query    = (const float*)d_in[0]; // (B,1,H)
    const float* proj_key = (const float*)d_in[1]; // (B,S,H)
    const float* enc      = (const float*)d_in[2]; // (B,S,K)
    const int*   mask     = (const int*)  d_in[3]; // (B,1,S)
    const float* Wq       = (const float*)d_in[4]; // (H,H)
    const float* v        = (const float*)d_in[5]; // (H,)

    float* ctx    = (float*)d_out;              // (B,1,K)
    float* alphas = (float*)d_out + Bc*Kc;      // (B,1,S)

    qproj_kernel<<<dim3(Hc/8, Bc/QB), 256>>>(query, Wq);
    launch_pdl(score_kernel,           dim3((Bc*Sc)/16), dim3(256), proj_key, v);
    launch_pdl(softmax_kernel,         dim3(Bc),         dim3(256), mask, alphas);
    launch_pdl(context_partial_kernel, dim3(SCC, Bc),    dim3(256), enc, (const float*)alphas);
    launch_pdl(context_reduce_kernel,  dim3(Bc),         dim3(256), ctx);
}

// round 11
// speedup vs baseline: 1.0684x; 1.0040x over previous
#include <cuda_runtime.h>
#include <cooperative_groups.h>
#include <math.h>

namespace cg = cooperative_groups;

#define Bc 64
#define Sc 2048
#define Hc 512
#define Kc 1024
#define SCC 8              // context CTAs per b == cluster size
#define SCHUNK (Sc/SCC)    // 256 rows per context CTA
#define CTHREADS 512
#define QB 16              // query rows per qproj CTA

// Scratch (no allocations allowed in kernel_launch)
__device__ float g_q[Bc*Hc];            // 128 KB
__device__ float g_scores[Bc*Sc];       // 512 KB

// tanh(x) = 1 - 2/(exp(2x)+1); __expf ~2ulp -> overall ~1e-6 error.
__device__ __forceinline__ float fast_tanhf(float x) {
    float e = __expf(2.0f * x);
    return 1.0f - __fdividef(2.0f, e + 1.0f);
}

#if defined(__CUDA_ARCH__) && (__CUDA_ARCH__ >= 900)
#define GRID_DEP_SYNC() cudaGridDependencySynchronize()
#else
#define GRID_DEP_SYNC()
#endif

// ---------------------------------------------------------------------------
// K1: q[b,h] = sum_e query[b,e] * W_q[h,e]
// grid (Hc/8, Bc/QB) = (64, 4), block 256 (8 warps).
// ---------------------------------------------------------------------------
__global__ void qproj_kernel(const float* __restrict__ query,
                             const float* __restrict__ Wq) {
    __shared__ float sq[QB][Hc];            // 32 KB
    const int t = threadIdx.x;
    const int warp = t >> 5, lane = t & 31;
    const int h  = blockIdx.x * 8 + warp;
    const int b0 = blockIdx.y * QB;

    const float4* wrow = (const float4*)(Wq + (size_t)h * Hc);
    float4 w0 = wrow[lane];
    float4 w1 = wrow[lane + 32];
    float4 w2 = wrow[lane + 64];
    float4 w3 = wrow[lane + 96];

    {
        const float4* qsrc = (const float4*)(query + (size_t)b0 * Hc);
        float4* qdst = (float4*)&sq[0][0];
#pragma unroll
        for (int j = 0; j < (QB*Hc/4)/256; j++)
            qdst[t + 256*j] = qsrc[t + 256*j];
    }
    __syncthreads();

#pragma unroll
    for (int bb = 0; bb < QB; bb++) {
        const float* qr = sq[bb];
        int e0 = lane*4, e1 = (lane+32)*4, e2 = (lane+64)*4, e3 = (lane+96)*4;
        float acc;
        acc = w0.x*qr[e0]   + w0.y*qr[e0+1] + w0.z*qr[e0+2] + w0.w*qr[e0+3];
        acc = fmaf(w1.x, qr[e1], acc); acc = fmaf(w1.y, qr[e1+1], acc);
        acc = fmaf(w1.z, qr[e1+2], acc); acc = fmaf(w1.w, qr[e1+3], acc);
        acc = fmaf(w2.x, qr[e2], acc); acc = fmaf(w2.y, qr[e2+1], acc);
        acc = fmaf(w2.z, qr[e2+2], acc); acc = fmaf(w2.w, qr[e2+3], acc);
        acc = fmaf(w3.x, qr[e3], acc); acc = fmaf(w3.y, qr[e3+1], acc);
        acc = fmaf(w3.z, qr[e3+2], acc); acc = fmaf(w3.w, qr[e3+3], acc);
#pragma unroll
        for (int o = 16; o; o >>= 1) acc += __shfl_xor_sync(0xffffffffu, acc, o);
        if (lane == 0) g_q[(b0 + bb)*Hc + h] = acc;
    }
}

// ---------------------------------------------------------------------------
// K2: scores[b,s] = sum_h tanh(q[b,h] + pk[b,s,h]) * v[h]
// block 256 (8 warps), warp handles 2 rows -> 16 rows/block, 8192 blocks.
// ---------------------------------------------------------------------------
__global__ void score_kernel(const float* __restrict__ pk,
                             const float* __restrict__ v) {
    __shared__ float sq[Hc];
    __shared__ float sv[Hc];
    const int t = threadIdx.x;
    const int row0 = blockIdx.x * 16;
    const int b = row0 >> 11;               // blocks don't straddle b
    sv[t]       = v[t];                     // input: no dependency
    sv[t + 256] = v[t + 256];
    GRID_DEP_SYNC();                        // wait for qproj's g_q
    sq[t]       = g_q[b*Hc + t];
    sq[t + 256] = g_q[b*Hc + t + 256];
    __syncthreads();

    const int warp = t >> 5, lane = t & 31;
    const int rowA = row0 + warp*2;
    const int rowB = rowA + 1;
    const float4* pA = (const float4*)(pk + (size_t)rowA * Hc);
    const float4* pB = (const float4*)(pk + (size_t)rowB * Hc);
    float accA = 0.0f, accB = 0.0f;
#pragma unroll
    for (int i = 0; i < 4; i++) {
        float4 a = pA[lane + 32*i];
        float4 c = pB[lane + 32*i];
        int e = (lane + 32*i) * 4;
        float q0 = sq[e], q1 = sq[e+1], q2 = sq[e+2], q3 = sq[e+3];
        float v0 = sv[e], v1 = sv[e+1], v2 = sv[e+2], v3 = sv[e+3];
        accA = fmaf(fast_tanhf(a.x + q0), v0, accA);
        accA = fmaf(fast_tanhf(a.y + q1), v1, accA);
        accA = fmaf(fast_tanhf(a.z + q2), v2, accA);
        accA = fmaf(fast_tanhf(a.w + q3), v3, accA);
        accB = fmaf(fast_tanhf(c.x + q0), v0, accB);
        accB = fmaf(fast_tanhf(c.y + q1), v1, accB);
        accB = fmaf(fast_tanhf(c.z + q2), v2, accB);
        accB = fmaf(fast_tanhf(c.w + q3), v3, accB);
    }
#pragma unroll
    for (int o = 16; o; o >>= 1) {
        accA += __shfl_xor_sync(0xffffffffu, accA, o);
        accB += __shfl_xor_sync(0xffffffffu, accB, o);
    }
    if (lane == 0) {
        g_scores[rowA] = accA;
        g_scores[rowB] = accB;
    }
}

// ---------------------------------------------------------------------------
// K3: masked softmax over s for each b. grid Bc, block 256, 8 values/thread.
// ---------------------------------------------------------------------------
__global__ void softmax_kernel(const int* __restrict__ mask,
                               float* __restrict__ alphas_out) {
    const int b = blockIdx.x, t = threadIdx.x;
    __shared__ float red[8];

    int m[8];
#pragma unroll
    for (int i = 0; i < 8; i++) m[i] = mask[b*Sc + t + 256*i];

    GRID_DEP_SYNC();                        // wait for g_scores

    float vals[8];
    float mx = -INFINITY;
#pragma unroll
    for (int i = 0; i < 8; i++) {
        float x = g_scores[b*Sc + t + 256*i];
        if (m[i] == 0) x = -INFINITY;
        vals[i] = x;
        mx = fmaxf(mx, x);
    }
#pragma unroll
    for (int o = 16; o; o >>= 1) mx = fmaxf(mx, __shfl_xor_sync(0xffffffffu, mx, o));
    if ((t & 31) == 0) red[t >> 5] = mx;
    __syncthreads();
    mx = red[0];
#pragma unroll
    for (int i = 1; i < 8; i++) mx = fmaxf(mx, red[i]);

    float sum = 0.0f;
#pragma unroll
    for (int i = 0; i < 8; i++) {
        float e = __expf(vals[i] - mx);
        vals[i] = e;
        sum += e;
    }
#pragma unroll
    for (int o = 16; o; o >>= 1) sum += __shfl_xor_sync(0xffffffffu, sum, o);
    __syncthreads();
    if ((t & 31) == 0) red[t >> 5] = sum;
    __syncthreads();
    float tot = red[0];
#pragma unroll
    for (int i = 1; i < 8; i++) tot += red[i];
    float inv = 1.0f / tot;
#pragma unroll
    for (int i = 0; i < 8; i++)
        alphas_out[b*Sc + t + 256*i] = vals[i] * inv;
}

// ---------------------------------------------------------------------------
// K4: context with in-cluster reduction. grid (SCC, Bc) = (8, 64), 512 thr,
// cluster (8,1,1) = one cluster per b.
//  - thread t owns k-slot (t&255) and s-half (t>>8); 128 rows each
//  - halves combined via smem -> per-CTA partial in spart[] (smem)
//  - cluster.sync, then 8-rank DSMEM shfl-tree (fixed order, deterministic):
//    thread t<256 reads slot (c*32 + t>>3) from rank (t&7), reduces in
//    8-lane segments, rank-0 lane writes ctx. No g_part, no reduce kernel.
// ---------------------------------------------------------------------------
__global__ void __cluster_dims__(SCC, 1, 1)
context_cluster_kernel(const float* __restrict__ eh,
                       const float* __restrict__ alphas,
                       float* __restrict__ ctx_out) {
    __shared__ float  sa[SCHUNK];           // 1 KB
    __shared__ float4 shalf[Kc/4];          // 4 KB
    __shared__ float4 spart[Kc/4];          // 4 KB
    cg::cluster_group cl = cg::this_cluster();
    const int c = blockIdx.x;               // == cluster rank
    const int b = blockIdx.y;
    const int t = threadIdx.x;
    const int slot = t & 255;
    const int half = t >> 8;                // 0 or 1

    GRID_DEP_SYNC();                        // wait for alphas (softmax output)
    if (t < SCHUNK) sa[t] = alphas[b*Sc + c*SCHUNK + t];
    __syncthreads();

    const float4* base =
        (const float4*)(eh + ((size_t)(b*Sc + c*SCHUNK + half*128)) * Kc) + slot;
    const float* sah = sa + half*128;
    float4 acc = make_float4(0.f, 0.f, 0.f, 0.f);
#pragma unroll 8
    for (int s = 0; s < 128; s++) {
        float a = sah[s];
        float4 vv = base[(size_t)s * (Kc/4)];
        acc.x = fmaf(a, vv.x, acc.x);
        acc.y = fmaf(a, vv.y, acc.y);
        acc.z = fmaf(a, vv.z, acc.z);
        acc.w = fmaf(a, vv.w, acc.w);
    }

    // combine the two s-halves (fixed order: half0 + half1)
    if (half == 1) shalf[slot] = acc;
    __syncthreads();
    if (half == 0) {
        float4 o = shalf[slot];
        acc.x += o.x; acc.y += o.y; acc.z += o.z; acc.w += o.w;
        spart[slot] = acc;
    }
    cl.sync();                              // all partials visible cluster-wide

    // 8-rank DSMEM reduction: threads 0..255, 8 threads per slot
    if (t < 256) {
        const int myslot = c*32 + (t >> 3); // this CTA's 32-slot stripe
        const int src    = t & 7;           // source rank
        const float4* rp = cl.map_shared_rank(spart, src);
        float4 v = rp[myslot];
#pragma unroll
        for (int o = 4; o; o >>= 1) {       // reduce within 8-lane segments
            v.x += __shfl_down_sync(0xffffffffu, v.x, o, 8);
            v.y += __shfl_down_sync(0xffffffffu, v.y, o, 8);
            v.z += __shfl_down_sync(0xffffffffu, v.z, o, 8);
            v.w += __shfl_down_sync(0xffffffffu, v.w, o, 8);
        }
        if (src == 0)
            ((float4*)ctx_out)[(size_t)b * (Kc/4) + myslot] = v;
    }
    cl.sync();                              // peers done reading our smem
}

// ---------------------------------------------------------------------------
template <typename K, typename... Args>
static inline void launch_pdl(K kernel, dim3 grid, dim3 block, Args... args) {
    cudaLaunchAttribute attr[1];
    attr[0].id = cudaLaunchAttributeProgrammaticStreamSerialization;
    attr[0].val.programmaticStreamSerializationAllowed = 1;
    cudaLaunchConfig_t cfg;
    cfg.gridDim = grid;
    cfg.blockDim = block;
    cfg.dynamicSmemBytes = 0;
    cfg.stream = 0;
    cfg.attrs = attr;
    cfg.numAttrs = 1;
    cudaLaunchKernelEx(&cfg, kernel, args...);
}

extern "C" void kernel_launch(void* const* d_in, const int* in_sizes, int n_in,
                              void* d_out, int out_size) {
    const float* query    = (const float*)d_in[0]; // (B,1,H)
    const float* proj_key = (const float*)d_in[1]; // (B,S,H)
    const float* enc      = (const float*)d_in[2]; // (B,S,K)
    const int*   mask     = (const int*)  d_in[3]; // (B,1,S)
    const float* Wq       = (const float*)d_in[4]; // (H,H)
    const float* v        = (const float*)d_in[5]; // (H,)

    float* ctx    = (float*)d_out;              // (B,1,K)
    float* alphas = (float*)d_out + Bc*Kc;      // (B,1,S)

    qproj_kernel<<<dim3(Hc/8, Bc/QB), 256>>>(query, Wq);
    launch_pdl(score_kernel,           dim3((Bc*Sc)/16), dim3(256), proj_key, v);
    launch_pdl(softmax_kernel,         dim3(Bc),         dim3(256), mask, alphas);
    launch_pdl(context_cluster_kernel, dim3(SCC, Bc),    dim3(CTHREADS), enc,
               (const float*)alphas, ctx);
}